// round 6
// baseline (speedup 1.0000x reference)
#include <cuda_runtime.h>
#include <math.h>

#define NN 100000     // nodes
#define NE 800000     // edges
#define FD 128        // feature dim (in = hidden = 128)
#define NG 128        // graphs
#define NC 10         // classes
#define BN_EPS 1e-5f

// ---------------- device scratch (no allocation allowed) ----------------
__device__ float g_bufA[(size_t)NN * FD];   // aggregation accumulator
__device__ float g_bufB[(size_t)NN * FD];   // MLP hidden
__device__ float g_bufC[(size_t)NN * FD];   // MLP out (pre-BN)
__device__ float g_bufD[(size_t)NN * FD];   // post BN+ReLU (scatter source, conv2)
__device__ float g_sum[FD];
__device__ float g_sumsq[FD];
__device__ float g_scale[FD];
__device__ float g_shift[FD];
__device__ float g_pooled[NG * FD];
__device__ float g_counts[NG];

// ---------------- small zero kernels ----------------
__global__ void zero_all_k() {
    int i = blockIdx.x * blockDim.x + threadIdx.x;
    if (i < FD) { g_sum[i] = 0.f; g_sumsq[i] = 0.f; }
    if (i < NG) g_counts[i] = 0.f;
    if (i < NG * FD) g_pooled[i] = 0.f;
}

__global__ void zero_sums_k() {
    int i = threadIdx.x;
    if (i < FD) { g_sum[i] = 0.f; g_sumsq[i] = 0.f; }
}

// ---------------- copy (init accumulator = (1+eps)*x with eps=0) ----------------
__global__ void copy_k(const float4* __restrict__ src, float4* __restrict__ dst, int n4) {
    int i = blockIdx.x * blockDim.x + threadIdx.x;
    if (i < n4) dst[i] = src[i];
}

// ---------------- edge scatter-add: acc[dst] += feat[src] ----------------
// one warp per edge; each lane handles one float4 chunk of the 128-float row
// NOTE: edge_index arrives as int32 (harness converts int64 inputs to int32).
__global__ void scatter_k(const float* __restrict__ feat, float* __restrict__ acc,
                          const int* __restrict__ ei) {
    long long t = (long long)blockIdx.x * blockDim.x + threadIdx.x;
    int e = (int)(t >> 5);
    if (e >= NE) return;
    int c = (int)(t & 31);
    int s = ei[e];
    int d = ei[NE + e];
    if ((unsigned)s >= NN || (unsigned)d >= NN) return;  // defensive
    float4 v = ((const float4*)feat)[(size_t)s * 32 + c];
    float* p = acc + (size_t)d * FD + c * 4;
    asm volatile("red.global.add.v4.f32 [%0], {%1, %2, %3, %4};"
                 :: "l"(p), "f"(v.x), "f"(v.y), "f"(v.z), "f"(v.w) : "memory");
}

// ---------------- fp32 GEMM: C[M,128] = (A[M,128] @ W[128,128]) + b, optional ReLU ------
// 64 rows per block, 256 threads, each thread computes 8 rows x 4 cols.
// smem: W full tile (64KB) + A tile (32KB) = 96KB dynamic.
__global__ void gemm_k(const float* __restrict__ A, const float* __restrict__ W,
                       const float* __restrict__ bias, float* __restrict__ C, int relu) {
    extern __shared__ float sh[];
    float4* Wsh4 = (float4*)sh;               // 128*32 float4
    float* Ash = sh + FD * FD;                // 64*128 floats
    int tid = threadIdx.x;

    const float4* W4 = (const float4*)W;
    #pragma unroll
    for (int i = tid; i < FD * 32; i += 256) Wsh4[i] = W4[i];

    int row0 = blockIdx.x * 64;
    const float4* A4 = (const float4*)A;
    float4* Ash4 = (float4*)Ash;
    for (int i = tid; i < 64 * 32; i += 256) {
        int r = row0 + (i >> 5);
        Ash4[i] = (r < NN) ? A4[(size_t)r * 32 + (i & 31)] : make_float4(0.f, 0.f, 0.f, 0.f);
    }
    __syncthreads();

    int rg = tid >> 5;    // 0..7  (row group of 8)
    int cg = tid & 31;    // 0..31 (col group of 4)
    float4 bv = ((const float4*)bias)[cg];
    float acc[8][4];
    #pragma unroll
    for (int i = 0; i < 8; i++) {
        acc[i][0] = bv.x; acc[i][1] = bv.y; acc[i][2] = bv.z; acc[i][3] = bv.w;
    }

    #pragma unroll 4
    for (int k = 0; k < FD; k++) {
        float4 w = Wsh4[k * 32 + cg];
        #pragma unroll
        for (int i = 0; i < 8; i++) {
            float a = Ash[(rg * 8 + i) * FD + k];
            acc[i][0] = fmaf(a, w.x, acc[i][0]);
            acc[i][1] = fmaf(a, w.y, acc[i][1]);
            acc[i][2] = fmaf(a, w.z, acc[i][2]);
            acc[i][3] = fmaf(a, w.w, acc[i][3]);
        }
    }

    #pragma unroll
    for (int i = 0; i < 8; i++) {
        int r = row0 + rg * 8 + i;
        if (r < NN) {
            float4 o;
            o.x = acc[i][0]; o.y = acc[i][1]; o.z = acc[i][2]; o.w = acc[i][3];
            if (relu) {
                o.x = fmaxf(o.x, 0.f); o.y = fmaxf(o.y, 0.f);
                o.z = fmaxf(o.z, 0.f); o.w = fmaxf(o.w, 0.f);
            }
            ((float4*)C)[(size_t)r * 32 + cg] = o;
        }
    }
}

// ---------------- BN statistics: per-feature sum and sum of squares ----------------
__global__ void bnstats_k(const float* __restrict__ X) {
    int f = threadIdx.x;  // 128 threads = 128 features
    int chunk = (NN + gridDim.x - 1) / gridDim.x;
    int r0 = blockIdx.x * chunk;
    int r1 = min(r0 + chunk, NN);
    float a = 0.f, b = 0.f;
    for (int r = r0; r < r1; r++) {
        float v = X[(size_t)r * FD + f];
        a += v;
        b = fmaf(v, v, b);
    }
    atomicAdd(&g_sum[f], a);
    atomicAdd(&g_sumsq[f], b);
}

// ---------------- BN finalize: scale/shift from sums ----------------
__global__ void bnfin_k(const float* __restrict__ gamma, const float* __restrict__ beta) {
    int f = threadIdx.x;
    float mean = g_sum[f] * (1.f / NN);
    float var = g_sumsq[f] * (1.f / NN) - mean * mean;
    float sc = gamma[f] * rsqrtf(var + BN_EPS);
    g_scale[f] = sc;
    g_shift[f] = beta[f] - mean * sc;
}

// ---------------- BN+ReLU, write to two buffers (scatter src + accumulator init) ----
__global__ void bnrelu2_k(const float4* __restrict__ X, float4* __restrict__ o1,
                          float4* __restrict__ o2) {
    int i = blockIdx.x * blockDim.x + threadIdx.x;
    if (i >= NN * 32) return;
    int f = i & 31;
    float4 sc = ((const float4*)g_scale)[f];
    float4 sf = ((const float4*)g_shift)[f];
    float4 x = X[i];
    float4 v;
    v.x = fmaxf(fmaf(x.x, sc.x, sf.x), 0.f);
    v.y = fmaxf(fmaf(x.y, sc.y, sf.y), 0.f);
    v.z = fmaxf(fmaf(x.z, sc.z, sf.z), 0.f);
    v.w = fmaxf(fmaf(x.w, sc.w, sf.w), 0.f);
    o1[i] = v;
    o2[i] = v;
}

// ---------------- BN+ReLU fused with graph pooling (atomic segment sum) ----------------
// NOTE: batch arrives as int32.
__global__ void bnpool_k(const float4* __restrict__ X, const int* __restrict__ batch) {
    int i = blockIdx.x * blockDim.x + threadIdx.x;
    if (i >= NN * 32) return;
    int f = i & 31;
    int node = i >> 5;
    float4 sc = ((const float4*)g_scale)[f];
    float4 sf = ((const float4*)g_shift)[f];
    float4 x = X[i];
    float4 v;
    v.x = fmaxf(fmaf(x.x, sc.x, sf.x), 0.f);
    v.y = fmaxf(fmaf(x.y, sc.y, sf.y), 0.f);
    v.z = fmaxf(fmaf(x.z, sc.z, sf.z), 0.f);
    v.w = fmaxf(fmaf(x.w, sc.w, sf.w), 0.f);
    int g = batch[node];
    if ((unsigned)g >= NG) return;  // defensive
    float* p = g_pooled + (size_t)g * FD + f * 4;
    asm volatile("red.global.add.v4.f32 [%0], {%1, %2, %3, %4};"
                 :: "l"(p), "f"(v.x), "f"(v.y), "f"(v.z), "f"(v.w) : "memory");
}

// ---------------- per-graph node counts ----------------
__global__ void count_k(const int* __restrict__ batch) {
    int i = blockIdx.x * blockDim.x + threadIdx.x;
    if (i < NN) {
        int g = batch[i];
        if ((unsigned)g < NG) atomicAdd(&g_counts[g], 1.f);
    }
}

// ---------------- classifier + log_softmax, one thread per graph ----------------
__global__ void final_k(const float* __restrict__ Wlin, const float* __restrict__ blin,
                        float* __restrict__ out) {
    __shared__ float Ws[FD * NC];
    __shared__ float bs[NC];
    int t = threadIdx.x;
    for (int i = t; i < FD * NC; i += 128) Ws[i] = Wlin[i];
    if (t < NC) bs[t] = blin[t];
    __syncthreads();

    int g = t;  // 128 threads, one per graph
    float inv = 1.f / fmaxf(g_counts[g], 1.f);
    float logits[NC];
    #pragma unroll
    for (int c = 0; c < NC; c++) logits[c] = bs[c];
    for (int k = 0; k < FD; k++) {
        float p = g_pooled[(size_t)g * FD + k] * inv;
        #pragma unroll
        for (int c = 0; c < NC; c++) logits[c] = fmaf(p, Ws[k * NC + c], logits[c]);
    }
    float m = logits[0];
    #pragma unroll
    for (int c = 1; c < NC; c++) m = fmaxf(m, logits[c]);
    float s = 0.f;
    #pragma unroll
    for (int c = 0; c < NC; c++) s += expf(logits[c] - m);
    float lse = m + logf(s);
    #pragma unroll
    for (int c = 0; c < NC; c++) out[(size_t)g * NC + c] = logits[c] - lse;
}

// ---------------- host launcher ----------------
extern "C" void kernel_launch(void* const* d_in, const int* in_sizes, int n_in,
                              void* d_out, int out_size) {
    const float* x = (const float*)d_in[0];
    const int* ei = (const int*)d_in[1];       // int64 in reference -> int32 from harness
    const int* batch = (const int*)d_in[2];    // int64 in reference -> int32 from harness
    const float* W1a = (const float*)d_in[3];
    const float* b1a = (const float*)d_in[4];
    const float* W1b = (const float*)d_in[5];
    const float* b1b = (const float*)d_in[6];
    const float* gamma1 = (const float*)d_in[7];
    const float* beta1 = (const float*)d_in[8];
    const float* W2a = (const float*)d_in[9];
    const float* b2a = (const float*)d_in[10];
    const float* W2b = (const float*)d_in[11];
    const float* b2b = (const float*)d_in[12];
    const float* gamma2 = (const float*)d_in[13];
    const float* beta2 = (const float*)d_in[14];
    const float* Wlin = (const float*)d_in[15];
    const float* blin = (const float*)d_in[16];
    float* out = (float*)d_out;

    float *bufA, *bufB, *bufC, *bufD;
    cudaGetSymbolAddress((void**)&bufA, g_bufA);
    cudaGetSymbolAddress((void**)&bufB, g_bufB);
    cudaGetSymbolAddress((void**)&bufC, g_bufC);
    cudaGetSymbolAddress((void**)&bufD, g_bufD);

    cudaFuncSetAttribute(gemm_k, cudaFuncAttributeMaxDynamicSharedMemorySize, 98304);

    const int n4 = NN * 32;                  // float4 count of a node-feature matrix
    const int EW_BLOCKS = (n4 + 255) / 256;  // elementwise grid
    const int SC_BLOCKS = (NE * 32 + 255) / 256;
    const int GM_BLOCKS = (NN + 63) / 64;
    const size_t GM_SMEM = (size_t)(FD * FD + 64 * FD) * sizeof(float);

    // zero accumulators (pooled, counts, BN sums)
    zero_all_k<<<(NG * FD + 255) / 256, 256>>>();

    // ---- conv1 ----
    copy_k<<<EW_BLOCKS, 256>>>((const float4*)x, (float4*)bufA, n4);
    scatter_k<<<SC_BLOCKS, 256>>>(x, bufA, ei);
    gemm_k<<<GM_BLOCKS, 256, GM_SMEM>>>(bufA, W1a, b1a, bufB, 1);
    gemm_k<<<GM_BLOCKS, 256, GM_SMEM>>>(bufB, W1b, b1b, bufC, 0);
    bnstats_k<<<800, 128>>>(bufC);
    bnfin_k<<<1, 128>>>(gamma1, beta1);
    zero_sums_k<<<1, 128>>>();
    bnrelu2_k<<<EW_BLOCKS, 256>>>((const float4*)bufC, (float4*)bufD, (float4*)bufA);

    // ---- conv2 ----
    scatter_k<<<SC_BLOCKS, 256>>>(bufD, bufA, ei);
    gemm_k<<<GM_BLOCKS, 256, GM_SMEM>>>(bufA, W2a, b2a, bufB, 1);
    gemm_k<<<GM_BLOCKS, 256, GM_SMEM>>>(bufB, W2b, b2b, bufC, 0);
    bnstats_k<<<800, 128>>>(bufC);
    bnfin_k<<<1, 128>>>(gamma2, beta2);

    // ---- BN+ReLU fused with pooling, then classifier ----
    bnpool_k<<<EW_BLOCKS, 256>>>((const float4*)bufC, batch);
    count_k<<<(NN + 255) / 256, 256>>>(batch);
    final_k<<<1, 128>>>(Wlin, blin, out);
}

// round 9
// speedup vs baseline: 1.4110x; 1.4110x over previous
#include <cuda_runtime.h>
#include <math.h>
#include <cstdint>

#define NN 100000     // nodes
#define NE 800000     // edges
#define FD 128        // feature dim (in = hidden = 128)
#define NG 128        // graphs
#define NC 10         // classes
#define BN_EPS 1e-5f

// ---------------- device scratch (no allocation allowed) ----------------
__device__ float g_bufA[(size_t)NN * FD];   // aggregation accumulator
__device__ float g_bufB[(size_t)NN * FD];   // MLP hidden
__device__ float g_bufC[(size_t)NN * FD];   // MLP out (pre-BN)
__device__ float g_bufD[(size_t)NN * FD];   // post BN+ReLU (scatter source, conv2)
__device__ float g_sum[FD];
__device__ float g_sumsq[FD];
__device__ float g_scale[FD];
__device__ float g_shift[FD];
__device__ float g_pooled[NG * FD];
__device__ float g_counts[NG];

// ================= tf32 mma.sync GEMM (arch-agnostic PTX, works on compute_103) ========
// C[M,128] = A[M,128] @ W[128,128] (+bias, opt ReLU)
// CTA: 256 threads / 8 warps, tile 128x128. Warp tile: 32(M) x 64(N).
// mma.sync.m16n8k8 tf32: per k-step each warp does 2x8 = 16 MMAs.
// Smem tiles padded to stride 136 floats: B-frag reads conflict-free, A-frag 2-way.

#define SM_STRIDE 136
#define SM_TILE (128 * SM_STRIDE)            // floats per tile
#define GEMM_SMEM ((2 * SM_TILE + FD) * 4)   // A + W + bias

__device__ __forceinline__ uint32_t f2tf32(float f) {
    uint32_t u;
    asm("cvt.rna.tf32.f32 %0, %1;" : "=r"(u) : "f"(f));
    return u;
}

#define MMA_TF32(Cf, Af, Bf)                                                   \
    asm volatile("mma.sync.aligned.m16n8k8.row.col.f32.tf32.tf32.f32 "         \
                 "{%0,%1,%2,%3}, {%4,%5,%6,%7}, {%8,%9}, {%0,%1,%2,%3};"       \
                 : "+f"((Cf)[0]), "+f"((Cf)[1]), "+f"((Cf)[2]), "+f"((Cf)[3])  \
                 : "r"((Af)[0]), "r"((Af)[1]), "r"((Af)[2]), "r"((Af)[3]),     \
                   "r"((Bf)[0]), "r"((Bf)[1]))

__global__ void __launch_bounds__(256, 1)
gemm_tc_k(const float* __restrict__ A, const float* __restrict__ W,
          const float* __restrict__ bias, float* __restrict__ C, int relu) {
    extern __shared__ float sh[];
    float* As = sh;                  // [128][136] tf32 bit patterns
    float* Ws = sh + SM_TILE;        // [128][136]
    float* bs = sh + 2 * SM_TILE;    // [128]

    int tid = threadIdx.x;
    int wid = tid >> 5;
    int lid = tid & 31;
    int row0 = blockIdx.x * 128;

    if (tid < FD) bs[tid] = bias[tid];

    // ---- load tiles: each warp handles rows wid, wid+8, ... (coalesced ldg.128) ----
    const float4* A4 = (const float4*)A;
    const float4* W4 = (const float4*)W;
    #pragma unroll
    for (int it = 0; it < 16; it++) {
        int r = it * 8 + wid;          // 0..127
        int gr = row0 + r;
        float4 v = (gr < NN) ? A4[(size_t)gr * 32 + lid] : make_float4(0.f, 0.f, 0.f, 0.f);
        uint4 t;
        t.x = f2tf32(v.x); t.y = f2tf32(v.y); t.z = f2tf32(v.z); t.w = f2tf32(v.w);
        *(uint4*)&As[r * SM_STRIDE + lid * 4] = t;

        float4 w = W4[(size_t)r * 32 + lid];   // W[r][4*lid..4*lid+3]
        uint4 tw;
        tw.x = f2tf32(w.x); tw.y = f2tf32(w.y); tw.z = f2tf32(w.z); tw.w = f2tf32(w.w);
        *(uint4*)&Ws[r * SM_STRIDE + lid * 4] = tw;
    }
    __syncthreads();

    // ---- compute ----
    int warp_m = wid & 3;      // 0..3  -> M block of 32
    int warp_n = wid >> 2;     // 0..1  -> N block of 64
    int tig = lid & 3;         // thread-in-group
    int gid = lid >> 2;        // group id (0..7)

    float c[2][8][4];
    #pragma unroll
    for (int mt = 0; mt < 2; mt++)
        #pragma unroll
        for (int nt = 0; nt < 8; nt++)
            #pragma unroll
            for (int j = 0; j < 4; j++) c[mt][nt][j] = 0.f;

    #pragma unroll 4
    for (int k0 = 0; k0 < 16; k0++) {
        int kc = k0 * 8 + tig;
        uint32_t a[2][4];
        #pragma unroll
        for (int mt = 0; mt < 2; mt++) {
            int rb = warp_m * 32 + mt * 16 + gid;
            a[mt][0] = __float_as_uint(As[rb * SM_STRIDE + kc]);
            a[mt][1] = __float_as_uint(As[(rb + 8) * SM_STRIDE + kc]);
            a[mt][2] = __float_as_uint(As[rb * SM_STRIDE + kc + 4]);
            a[mt][3] = __float_as_uint(As[(rb + 8) * SM_STRIDE + kc + 4]);
        }
        uint32_t b[8][2];
        #pragma unroll
        for (int nt = 0; nt < 8; nt++) {
            int n = warp_n * 64 + nt * 8 + gid;
            b[nt][0] = __float_as_uint(Ws[kc * SM_STRIDE + n]);
            b[nt][1] = __float_as_uint(Ws[(kc + 4) * SM_STRIDE + n]);
        }
        #pragma unroll
        for (int mt = 0; mt < 2; mt++)
            #pragma unroll
            for (int nt = 0; nt < 8; nt++)
                MMA_TF32(c[mt][nt], a[mt], b[nt]);
    }

    // ---- epilogue: bias + relu + float2 stores ----
    #pragma unroll
    for (int mt = 0; mt < 2; mt++) {
        int rg = row0 + warp_m * 32 + mt * 16 + gid;
        #pragma unroll
        for (int nt = 0; nt < 8; nt++) {
            int col = warp_n * 64 + nt * 8 + tig * 2;
            float2 o0, o1;
            o0.x = c[mt][nt][0] + bs[col];
            o0.y = c[mt][nt][1] + bs[col + 1];
            o1.x = c[mt][nt][2] + bs[col];
            o1.y = c[mt][nt][3] + bs[col + 1];
            if (relu) {
                o0.x = fmaxf(o0.x, 0.f); o0.y = fmaxf(o0.y, 0.f);
                o1.x = fmaxf(o1.x, 0.f); o1.y = fmaxf(o1.y, 0.f);
            }
            if (rg < NN)     *(float2*)&C[(size_t)rg * FD + col] = o0;
            if (rg + 8 < NN) *(float2*)&C[(size_t)(rg + 8) * FD + col] = o1;
        }
    }
}

// ---------------- small zero kernels ----------------
__global__ void zero_all_k() {
    int i = blockIdx.x * blockDim.x + threadIdx.x;
    if (i < FD) { g_sum[i] = 0.f; g_sumsq[i] = 0.f; }
    if (i < NG) g_counts[i] = 0.f;
    if (i < NG * FD) g_pooled[i] = 0.f;
}

__global__ void zero_sums_k() {
    int i = threadIdx.x;
    if (i < FD) { g_sum[i] = 0.f; g_sumsq[i] = 0.f; }
}

// ---------------- copy (init accumulator = (1+eps)*x with eps=0) ----------------
__global__ void copy_k(const float4* __restrict__ src, float4* __restrict__ dst, int n4) {
    int i = blockIdx.x * blockDim.x + threadIdx.x;
    if (i < n4) dst[i] = src[i];
}

// ---------------- edge scatter-add: acc[dst] += feat[src] ----------------
__global__ void scatter_k(const float* __restrict__ feat, float* __restrict__ acc,
                          const int* __restrict__ ei) {
    long long t = (long long)blockIdx.x * blockDim.x + threadIdx.x;
    int e = (int)(t >> 5);
    if (e >= NE) return;
    int c = (int)(t & 31);
    int s = ei[e];
    int d = ei[NE + e];
    if ((unsigned)s >= NN || (unsigned)d >= NN) return;  // defensive
    float4 v = ((const float4*)feat)[(size_t)s * 32 + c];
    float* p = acc + (size_t)d * FD + c * 4;
    asm volatile("red.global.add.v4.f32 [%0], {%1, %2, %3, %4};"
                 :: "l"(p), "f"(v.x), "f"(v.y), "f"(v.z), "f"(v.w) : "memory");
}

// ---------------- BN statistics ----------------
__global__ void bnstats_k(const float* __restrict__ X) {
    int f = threadIdx.x;
    int chunk = (NN + gridDim.x - 1) / gridDim.x;
    int r0 = blockIdx.x * chunk;
    int r1 = min(r0 + chunk, NN);
    float a = 0.f, b = 0.f;
    for (int r = r0; r < r1; r++) {
        float v = X[(size_t)r * FD + f];
        a += v;
        b = fmaf(v, v, b);
    }
    atomicAdd(&g_sum[f], a);
    atomicAdd(&g_sumsq[f], b);
}

// ---------------- BN finalize ----------------
__global__ void bnfin_k(const float* __restrict__ gamma, const float* __restrict__ beta) {
    int f = threadIdx.x;
    float mean = g_sum[f] * (1.f / NN);
    float var = g_sumsq[f] * (1.f / NN) - mean * mean;
    float sc = gamma[f] * rsqrtf(var + BN_EPS);
    g_scale[f] = sc;
    g_shift[f] = beta[f] - mean * sc;
}

// ---------------- BN+ReLU, write to two buffers ----------------
__global__ void bnrelu2_k(const float4* __restrict__ X, float4* __restrict__ o1,
                          float4* __restrict__ o2) {
    int i = blockIdx.x * blockDim.x + threadIdx.x;
    if (i >= NN * 32) return;
    int f = i & 31;
    float4 sc = ((const float4*)g_scale)[f];
    float4 sf = ((const float4*)g_shift)[f];
    float4 x = X[i];
    float4 v;
    v.x = fmaxf(fmaf(x.x, sc.x, sf.x), 0.f);
    v.y = fmaxf(fmaf(x.y, sc.y, sf.y), 0.f);
    v.z = fmaxf(fmaf(x.z, sc.z, sf.z), 0.f);
    v.w = fmaxf(fmaf(x.w, sc.w, sf.w), 0.f);
    o1[i] = v;
    o2[i] = v;
}

// ---------------- BN+ReLU fused with graph pooling ----------------
__global__ void bnpool_k(const float4* __restrict__ X, const int* __restrict__ batch) {
    int i = blockIdx.x * blockDim.x + threadIdx.x;
    if (i >= NN * 32) return;
    int f = i & 31;
    int node = i >> 5;
    float4 sc = ((const float4*)g_scale)[f];
    float4 sf = ((const float4*)g_shift)[f];
    float4 x = X[i];
    float4 v;
    v.x = fmaxf(fmaf(x.x, sc.x, sf.x), 0.f);
    v.y = fmaxf(fmaf(x.y, sc.y, sf.y), 0.f);
    v.z = fmaxf(fmaf(x.z, sc.z, sf.z), 0.f);
    v.w = fmaxf(fmaf(x.w, sc.w, sf.w), 0.f);
    int g = batch[node];
    if ((unsigned)g >= NG) return;  // defensive
    float* p = g_pooled + (size_t)g * FD + f * 4;
    asm volatile("red.global.add.v4.f32 [%0], {%1, %2, %3, %4};"
                 :: "l"(p), "f"(v.x), "f"(v.y), "f"(v.z), "f"(v.w) : "memory");
}

// ---------------- per-graph node counts ----------------
__global__ void count_k(const int* __restrict__ batch) {
    int i = blockIdx.x * blockDim.x + threadIdx.x;
    if (i < NN) {
        int g = batch[i];
        if ((unsigned)g < NG) atomicAdd(&g_counts[g], 1.f);
    }
}

// ---------------- classifier + log_softmax ----------------
__global__ void final_k(const float* __restrict__ Wlin, const float* __restrict__ blin,
                        float* __restrict__ out) {
    __shared__ float Ws[FD * NC];
    __shared__ float bs[NC];
    int t = threadIdx.x;
    for (int i = t; i < FD * NC; i += 128) Ws[i] = Wlin[i];
    if (t < NC) bs[t] = blin[t];
    __syncthreads();

    int g = t;
    float inv = 1.f / fmaxf(g_counts[g], 1.f);
    float logits[NC];
    #pragma unroll
    for (int c = 0; c < NC; c++) logits[c] = bs[c];
    for (int k = 0; k < FD; k++) {
        float p = g_pooled[(size_t)g * FD + k] * inv;
        #pragma unroll
        for (int c = 0; c < NC; c++) logits[c] = fmaf(p, Ws[k * NC + c], logits[c]);
    }
    float m = logits[0];
    #pragma unroll
    for (int c = 1; c < NC; c++) m = fmaxf(m, logits[c]);
    float s = 0.f;
    #pragma unroll
    for (int c = 0; c < NC; c++) s += expf(logits[c] - m);
    float lse = m + logf(s);
    #pragma unroll
    for (int c = 0; c < NC; c++) out[(size_t)g * NC + c] = logits[c] - lse;
}

// ---------------- host launcher ----------------
extern "C" void kernel_launch(void* const* d_in, const int* in_sizes, int n_in,
                              void* d_out, int out_size) {
    const float* x = (const float*)d_in[0];
    const int* ei = (const int*)d_in[1];
    const int* batch = (const int*)d_in[2];
    const float* W1a = (const float*)d_in[3];
    const float* b1a = (const float*)d_in[4];
    const float* W1b = (const float*)d_in[5];
    const float* b1b = (const float*)d_in[6];
    const float* gamma1 = (const float*)d_in[7];
    const float* beta1 = (const float*)d_in[8];
    const float* W2a = (const float*)d_in[9];
    const float* b2a = (const float*)d_in[10];
    const float* W2b = (const float*)d_in[11];
    const float* b2b = (const float*)d_in[12];
    const float* gamma2 = (const float*)d_in[13];
    const float* beta2 = (const float*)d_in[14];
    const float* Wlin = (const float*)d_in[15];
    const float* blin = (const float*)d_in[16];
    float* out = (float*)d_out;

    float *bufA, *bufB, *bufC, *bufD;
    cudaGetSymbolAddress((void**)&bufA, g_bufA);
    cudaGetSymbolAddress((void**)&bufB, g_bufB);
    cudaGetSymbolAddress((void**)&bufC, g_bufC);
    cudaGetSymbolAddress((void**)&bufD, g_bufD);

    cudaFuncSetAttribute(gemm_tc_k, cudaFuncAttributeMaxDynamicSharedMemorySize, GEMM_SMEM);

    const int n4 = NN * 32;
    const int EW_BLOCKS = (n4 + 255) / 256;
    const int SC_BLOCKS = (NE * 32 + 255) / 256;
    const int TC_BLOCKS = (NN + 127) / 128;

    zero_all_k<<<(NG * FD + 255) / 256, 256>>>();

    // ---- conv1 ----
    copy_k<<<EW_BLOCKS, 256>>>((const float4*)x, (float4*)bufA, n4);
    scatter_k<<<SC_BLOCKS, 256>>>(x, bufA, ei);
    gemm_tc_k<<<TC_BLOCKS, 256, GEMM_SMEM>>>(bufA, W1a, b1a, bufB, 1);
    gemm_tc_k<<<TC_BLOCKS, 256, GEMM_SMEM>>>(bufB, W1b, b1b, bufC, 0);
    bnstats_k<<<800, 128>>>(bufC);
    bnfin_k<<<1, 128>>>(gamma1, beta1);
    zero_sums_k<<<1, 128>>>();
    bnrelu2_k<<<EW_BLOCKS, 256>>>((const float4*)bufC, (float4*)bufD, (float4*)bufA);

    // ---- conv2 ----
    scatter_k<<<SC_BLOCKS, 256>>>(bufD, bufA, ei);
    gemm_tc_k<<<TC_BLOCKS, 256, GEMM_SMEM>>>(bufA, W2a, b2a, bufB, 1);
    gemm_tc_k<<<TC_BLOCKS, 256, GEMM_SMEM>>>(bufB, W2b, b2b, bufC, 0);
    bnstats_k<<<800, 128>>>(bufC);
    bnfin_k<<<1, 128>>>(gamma2, beta2);

    // ---- BN+ReLU fused with pooling, then classifier ----
    bnpool_k<<<EW_BLOCKS, 256>>>((const float4*)bufC, batch);
    count_k<<<(NN + 255) / 256, 256>>>(batch);
    final_k<<<1, 128>>>(Wlin, blin, out);
}